// round 2
// baseline (speedup 1.0000x reference)
#include <cuda_runtime.h>
#include <cstdint>

#define NPTS 1000000
#define WRES 64
// Transposed grids, layout [3, H, W, 16] per scale, concatenated.
// sizes (floats): s=1:393216  s=2:786432  s=4:1572864  s=8:3145728  total 5898240
__device__ float g_trans[5898240];

__device__ __constant__ int c_toff[4] = {0, 393216, 1179648, 2752512};

// -------- transpose: [3,16,H,64] -> [3,H,64,16] --------
__global__ void transpose_k(const float* __restrict__ g, int H, int toff) {
    int idx = blockIdx.x * blockDim.x + threadIdx.x;
    int total = 3 * H * WRES;
    if (idx >= total) return;
    int w = idx & 63;
    int rest = idx >> 6;          // ci*H + h
    int h = rest & (H - 1);       // H is power of two
    int ci = rest / H;
    const float* src = g + ((size_t)(ci * 16) * H + h) * WRES + w;
    float tmp[16];
    size_t fstride = (size_t)H * WRES;
#pragma unroll
    for (int f = 0; f < 16; f++) tmp[f] = src[f * fstride];
    float4* dst = reinterpret_cast<float4*>(g_trans + toff + (size_t)idx * 16);
    dst[0] = make_float4(tmp[0], tmp[1], tmp[2], tmp[3]);
    dst[1] = make_float4(tmp[4], tmp[5], tmp[6], tmp[7]);
    dst[2] = make_float4(tmp[8], tmp[9], tmp[10], tmp[11]);
    dst[3] = make_float4(tmp[12], tmp[13], tmp[14], tmp[15]);
}

// -------- main sample kernel: 12 threads per point --------
__global__ void __launch_bounds__(256) sample_k(const float* __restrict__ pts,
                                                const float* __restrict__ radius,
                                                float* __restrict__ out) {
    int tid = blockIdx.x * blockDim.x + threadIdx.x;
    if (tid >= NPTS * 12) return;
    int n = tid / 12;
    int j = tid - n * 12;       // j = sIdx*3 + ci
    int sIdx = j / 3;
    int ci = j - sIdx * 3;
    int H = 128 << sIdx;

    float x = pts[n * 3 + ci];
    float y = radius[n];

    float fx = (x + 1.0f) * 0.5f * (WRES - 1);
    float fy = (y + 1.0f) * 0.5f * (float)(H - 1);
    float x0f = floorf(fx);
    float y0f = floorf(fy);
    float wx = fx - x0f;
    float wy = fy - y0f;
    int x0 = min(max((int)x0f, 0), WRES - 1);
    int x1 = min(max((int)x0f + 1, 0), WRES - 1);
    int y0 = min(max((int)y0f, 0), H - 1);
    int y1 = min(max((int)y0f + 1, 0), H - 1);

    const float* t = g_trans + c_toff[sIdx];
    int rowbase0 = (ci * H + y0) * WRES;
    int rowbase1 = (ci * H + y1) * WRES;
    const float4* p00 = reinterpret_cast<const float4*>(t + (size_t)(rowbase0 + x0) * 16);
    const float4* p01 = reinterpret_cast<const float4*>(t + (size_t)(rowbase0 + x1) * 16);
    const float4* p10 = reinterpret_cast<const float4*>(t + (size_t)(rowbase1 + x0) * 16);
    const float4* p11 = reinterpret_cast<const float4*>(t + (size_t)(rowbase1 + x1) * 16);

    float w00 = (1.0f - wy) * (1.0f - wx);
    float w01 = (1.0f - wy) * wx;
    float w10 = wy * (1.0f - wx);
    float w11 = wy * wx;

    float4* o = reinterpret_cast<float4*>(out + (size_t)n * 192 + j * 16);
#pragma unroll
    for (int k = 0; k < 4; k++) {
        float4 a = p00[k];
        float4 b = p01[k];
        float4 c = p10[k];
        float4 d = p11[k];
        float4 r;
        r.x = a.x * w00 + b.x * w01 + c.x * w10 + d.x * w11;
        r.y = a.y * w00 + b.y * w01 + c.y * w10 + d.y * w11;
        r.z = a.z * w00 + b.z * w01 + c.z * w10 + d.z * w11;
        r.w = a.w * w00 + b.w * w01 + c.w * w10 + d.w * w11;
        o[k] = r;
    }
}

extern "C" void kernel_launch(void* const* d_in, const int* in_sizes, int n_in,
                              void* d_out, int out_size) {
    const float* pts    = (const float*)d_in[0];
    const float* radius = (const float*)d_in[1];
    float* out = (float*)d_out;

    // Transpose each scale's grid into g_trans
    const int toffs[4] = {0, 393216, 1179648, 2752512};
    for (int s = 0; s < 4; s++) {
        int H = 128 << s;
        int total = 3 * H * WRES;
        int blocks = (total + 255) / 256;
        transpose_k<<<blocks, 256>>>((const float*)d_in[2 + s], H, toffs[s]);
    }

    // Main sampling pass
    int totalThreads = NPTS * 12;
    int blocks = (totalThreads + 255) / 256;
    sample_k<<<blocks, 256>>>(pts, radius, out);
}

// round 3
// speedup vs baseline: 1.1306x; 1.1306x over previous
#include <cuda_runtime.h>
#include <cuda_fp16.h>
#include <cstdint>

#define NPTS 1000000
#define WRES 64

// Transposed grids in fp16, layout [3, H, W, 16] per scale, concatenated.
// per-scale half counts: s0 393216, s1 786432, s2 1572864, s3 3145728; total 5898240
__device__ __align__(16) __half g_trans[5898240];

// -------- transpose+convert: [3,16,H,64] fp32 -> [3,H,64,16] fp16 --------
__global__ void transpose_k(const float* __restrict__ g, int H, int toff) {
    int idx = blockIdx.x * blockDim.x + threadIdx.x;
    int total = 3 * H * WRES;
    if (idx >= total) return;
    int w = idx & 63;
    int rest = idx >> 6;          // ci*H + h
    int h = rest & (H - 1);       // H is power of two
    int ci = rest / H;
    const float* src = g + ((size_t)(ci * 16) * H + h) * WRES + w;
    float tmp[16];
    size_t fstride = (size_t)H * WRES;
#pragma unroll
    for (int f = 0; f < 16; f++) tmp[f] = src[f * fstride];

    __half2 hv[8];
#pragma unroll
    for (int f = 0; f < 8; f++) hv[f] = __floats2half2_rn(tmp[2 * f], tmp[2 * f + 1]);

    uint4* dst = reinterpret_cast<uint4*>(g_trans + toff + (size_t)idx * 16);
    uint4 a, b;
    a.x = *(uint32_t*)&hv[0]; a.y = *(uint32_t*)&hv[1];
    a.z = *(uint32_t*)&hv[2]; a.w = *(uint32_t*)&hv[3];
    b.x = *(uint32_t*)&hv[4]; b.y = *(uint32_t*)&hv[5];
    b.z = *(uint32_t*)&hv[6]; b.w = *(uint32_t*)&hv[7];
    dst[0] = a;
    dst[1] = b;
}

// -------- main sample kernel: 8 lanes per (point, j) group --------
// group G = n*12 + j;  j = sIdx*3 + ci
// lane r = (y<<2) | (xhi<<1) | half  : one LDG.128 of 8 fp16 feats per lane
__global__ void __launch_bounds__(256) sample_k(const float* __restrict__ pts,
                                                const float* __restrict__ radius,
                                                float* __restrict__ out) {
    int G = blockIdx.x * 32 + (threadIdx.x >> 3);
    int r = threadIdx.x & 7;
    int n = G / 12;
    int j = G - n * 12;
    int sIdx = j / 3;           // 0..3
    int ci = j - sIdx * 3;      // 0..2
    int H = 128 << sIdx;

    int y    = r >> 2;
    int xhi  = (r >> 1) & 1;
    int half = r & 1;

    float xv = pts[n * 3 + ci];
    float yv = radius[n];

    float fx = (xv + 1.0f) * 0.5f * 63.0f;
    float fy = (yv + 1.0f) * 0.5f * (float)(H - 1);
    float x0f = floorf(fx);
    float y0f = floorf(fy);
    float wx = fx - x0f;
    float wy = fy - y0f;
    int x0 = min(max((int)x0f, 0), 63);
    int x1 = min(x0 + 1, 63);
    int y0 = min(max((int)y0f, 0), H - 1);
    int y1 = min(y0 + 1, H - 1);

    int xs = xhi ? x1 : x0;
    int ys = y ? y1 : y0;
    float w = (y ? wy : (1.0f - wy)) * (xhi ? wx : (1.0f - wx));

    int toff = 393216 * ((1 << sIdx) - 1);
    const __half* t = g_trans + toff;
    const uint4* p = reinterpret_cast<const uint4*>(
        t + (size_t)((ci * H + ys) * WRES + xs) * 16 + half * 8);
    uint4 v = *p;

    float2 f0 = __half22float2(*(__half2*)&v.x);
    float2 f1 = __half22float2(*(__half2*)&v.y);
    float2 f2 = __half22float2(*(__half2*)&v.z);
    float2 f3 = __half22float2(*(__half2*)&v.w);

    float acc[8];
    acc[0] = f0.x * w; acc[1] = f0.y * w;
    acc[2] = f1.x * w; acc[3] = f1.y * w;
    acc[4] = f2.x * w; acc[5] = f2.y * w;
    acc[6] = f3.x * w; acc[7] = f3.y * w;

    // butterfly over x-corner (mask 2) then y-corner (mask 4)
#pragma unroll
    for (int i = 0; i < 8; i++) acc[i] += __shfl_xor_sync(0xffffffffu, acc[i], 2);
#pragma unroll
    for (int i = 0; i < 8; i++) acc[i] += __shfl_xor_sync(0xffffffffu, acc[i], 4);

    if (r < 2) {
        float4* o = reinterpret_cast<float4*>(out + (size_t)n * 192 + j * 16 + half * 8);
        o[0] = make_float4(acc[0], acc[1], acc[2], acc[3]);
        o[1] = make_float4(acc[4], acc[5], acc[6], acc[7]);
    }
}

extern "C" void kernel_launch(void* const* d_in, const int* in_sizes, int n_in,
                              void* d_out, int out_size) {
    const float* pts    = (const float*)d_in[0];
    const float* radius = (const float*)d_in[1];
    float* out = (float*)d_out;

    const int toffs[4] = {0, 393216, 1179648, 2752512};
    for (int s = 0; s < 4; s++) {
        int H = 128 << s;
        int total = 3 * H * WRES;
        int blocks = (total + 255) / 256;
        transpose_k<<<blocks, 256>>>((const float*)d_in[2 + s], H, toffs[s]);
    }

    // 12M groups * 8 lanes = 96M threads; 256 threads/block = 32 groups/block
    // 12,000,000 / 32 = 375,000 blocks exactly
    sample_k<<<375000, 256>>>(pts, radius, out);
}

// round 4
// speedup vs baseline: 1.7351x; 1.5346x over previous
#include <cuda_runtime.h>
#include <cuda_fp16.h>
#include <cstdint>

#define NPTS 1000000
#define WRES 64
#define NSAMP (NPTS * 12)

// Transposed grids in fp16, layout [3, H, W, 16] per scale, concatenated.
// per-scale half counts: s0 393216, s1 786432, s2 1572864, s3 3145728
__device__ __align__(16) __half g_trans[5898240];

// -------- fused transpose+convert: [3,16,H,64] fp32 -> [3,H,64,16] fp16, all scales --------
__global__ void __launch_bounds__(256) transpose_all(const float* __restrict__ g0,
                                                     const float* __restrict__ g1,
                                                     const float* __restrict__ g2,
                                                     const float* __restrict__ g3) {
    int idx = blockIdx.x * blockDim.x + threadIdx.x;
    if (idx >= 368640) return;   // 3*64*(128+256+512+1024)
    const float* g;
    int H, toff, local, hshift;
    if (idx < 24576)       { g = g0; H = 128;  toff = 0;       local = idx;          hshift = 7;  }
    else if (idx < 73728)  { g = g1; H = 256;  toff = 393216;  local = idx - 24576;  hshift = 8;  }
    else if (idx < 172032) { g = g2; H = 512;  toff = 1179648; local = idx - 73728;  hshift = 9;  }
    else                   { g = g3; H = 1024; toff = 2752512; local = idx - 172032; hshift = 10; }

    int w = local & 63;
    int rest = local >> 6;            // ci*H + h
    int h = rest & (H - 1);
    int ci = rest >> hshift;
    const float* src = g + ((size_t)(ci * 16) * H + h) * WRES + w;
    float tmp[16];
    size_t fstride = (size_t)H * WRES;
#pragma unroll
    for (int f = 0; f < 16; f++) tmp[f] = src[f * fstride];

    __half2 hv[8];
#pragma unroll
    for (int f = 0; f < 8; f++) hv[f] = __floats2half2_rn(tmp[2 * f], tmp[2 * f + 1]);

    uint4* dst = reinterpret_cast<uint4*>(g_trans + toff + (size_t)local * 16);
    uint4 a, b;
    a.x = *(uint32_t*)&hv[0]; a.y = *(uint32_t*)&hv[1];
    a.z = *(uint32_t*)&hv[2]; a.w = *(uint32_t*)&hv[3];
    b.x = *(uint32_t*)&hv[4]; b.y = *(uint32_t*)&hv[5];
    b.z = *(uint32_t*)&hv[6]; b.w = *(uint32_t*)&hv[7];
    dst[0] = a;
    dst[1] = b;
}

// -------- main sample kernel: one thread per (point n, sample j) --------
// j = sIdx*3 + ci. Thread loads 4 corners x 32B fp16, fp32 lerp, stores 64B.
__global__ void __launch_bounds__(256) sample_k(const float* __restrict__ pts,
                                                const float* __restrict__ radius,
                                                float* __restrict__ out) {
    int t = blockIdx.x * blockDim.x + threadIdx.x;
    if (t >= NSAMP) return;
    int n = t / 12;
    int j = t - n * 12;
    int sIdx = j / 3;             // 0..3
    int ci = j - sIdx * 3;        // 0..2
    int H = 128 << sIdx;

    float xv = pts[n * 3 + ci];
    float yv = __ldg(radius + n);

    float fx = (xv + 1.0f) * 0.5f * 63.0f;
    float fy = (yv + 1.0f) * 0.5f * (float)(H - 1);
    float x0f = floorf(fx);
    float y0f = floorf(fy);
    float wx = fx - x0f;
    float wy = fy - y0f;
    int x0 = min(max((int)x0f, 0), 63);
    int x1 = min(x0 + 1, 63);
    int y0 = min(max((int)y0f, 0), H - 1);
    int y1 = min(y0 + 1, H - 1);

    int toff = 393216 * ((1 << sIdx) - 1);
    const __half* tb = g_trans + toff + (size_t)(ci * H) * (WRES * 16);

    const uint4* p00 = reinterpret_cast<const uint4*>(tb + (size_t)(y0 * WRES + x0) * 16);
    const uint4* p01 = reinterpret_cast<const uint4*>(tb + (size_t)(y0 * WRES + x1) * 16);
    const uint4* p10 = reinterpret_cast<const uint4*>(tb + (size_t)(y1 * WRES + x0) * 16);
    const uint4* p11 = reinterpret_cast<const uint4*>(tb + (size_t)(y1 * WRES + x1) * 16);

    // 8 independent 16B loads -> MLP=8
    uint4 v[8];
    v[0] = p00[0]; v[1] = p00[1];
    v[2] = p01[0]; v[3] = p01[1];
    v[4] = p10[0]; v[5] = p10[1];
    v[6] = p11[0]; v[7] = p11[1];

    float w00 = (1.0f - wy) * (1.0f - wx);
    float w01 = (1.0f - wy) * wx;
    float w10 = wy * (1.0f - wx);
    float w11 = wy * wx;

    float acc[16];
    const __half2* h2 = reinterpret_cast<const __half2*>(v);
#pragma unroll
    for (int k = 0; k < 8; k++) {
        float2 f = __half22float2(h2[k]);
        acc[2 * k]     = f.x * w00;
        acc[2 * k + 1] = f.y * w00;
    }
#pragma unroll
    for (int k = 0; k < 8; k++) {
        float2 f = __half22float2(h2[8 + k]);
        acc[2 * k]     += f.x * w01;
        acc[2 * k + 1] += f.y * w01;
    }
#pragma unroll
    for (int k = 0; k < 8; k++) {
        float2 f = __half22float2(h2[16 + k]);
        acc[2 * k]     += f.x * w10;
        acc[2 * k + 1] += f.y * w10;
    }
#pragma unroll
    for (int k = 0; k < 8; k++) {
        float2 f = __half22float2(h2[24 + k]);
        acc[2 * k]     += f.x * w11;
        acc[2 * k + 1] += f.y * w11;
    }

    float4* o = reinterpret_cast<float4*>(out + (size_t)n * 192 + j * 16);
    o[0] = make_float4(acc[0],  acc[1],  acc[2],  acc[3]);
    o[1] = make_float4(acc[4],  acc[5],  acc[6],  acc[7]);
    o[2] = make_float4(acc[8],  acc[9],  acc[10], acc[11]);
    o[3] = make_float4(acc[12], acc[13], acc[14], acc[15]);
}

extern "C" void kernel_launch(void* const* d_in, const int* in_sizes, int n_in,
                              void* d_out, int out_size) {
    const float* pts    = (const float*)d_in[0];
    const float* radius = (const float*)d_in[1];
    float* out = (float*)d_out;

    transpose_all<<<(368640 + 255) / 256, 256>>>((const float*)d_in[2],
                                                 (const float*)d_in[3],
                                                 (const float*)d_in[4],
                                                 (const float*)d_in[5]);

    sample_k<<<(NSAMP + 255) / 256, 256>>>(pts, radius, out);
}

// round 5
// speedup vs baseline: 3.1088x; 1.7917x over previous
#include <cuda_runtime.h>
#include <cuda_fp16.h>
#include <cstdint>

#define NPTS 1000000
#define WRES 64
#define NSAMP (NPTS * 12)

// Transposed grids in fp16, layout [3, H, W, 16] per scale, concatenated.
__device__ __align__(16) __half g_trans[5898240];

// -------- fused transpose+convert: [3,16,H,64] fp32 -> [3,H,64,16] fp16 --------
__global__ void __launch_bounds__(256) transpose_all(const float* __restrict__ g0,
                                                     const float* __restrict__ g1,
                                                     const float* __restrict__ g2,
                                                     const float* __restrict__ g3) {
    int idx = blockIdx.x * blockDim.x + threadIdx.x;
    if (idx >= 368640) return;   // 3*64*(128+256+512+1024)
    const float* g;
    int H, toff, local, hshift;
    if (idx < 24576)       { g = g0; H = 128;  toff = 0;       local = idx;          hshift = 7;  }
    else if (idx < 73728)  { g = g1; H = 256;  toff = 393216;  local = idx - 24576;  hshift = 8;  }
    else if (idx < 172032) { g = g2; H = 512;  toff = 1179648; local = idx - 73728;  hshift = 9;  }
    else                   { g = g3; H = 1024; toff = 2752512; local = idx - 172032; hshift = 10; }

    int w = local & 63;
    int rest = local >> 6;            // ci*H + h
    int h = rest & (H - 1);
    int ci = rest >> hshift;
    const float* src = g + ((size_t)(ci * 16) * H + h) * WRES + w;
    float tmp[16];
    size_t fstride = (size_t)H * WRES;
#pragma unroll
    for (int f = 0; f < 16; f++) tmp[f] = src[f * fstride];

    __half2 hv[8];
#pragma unroll
    for (int f = 0; f < 8; f++) hv[f] = __floats2half2_rn(tmp[2 * f], tmp[2 * f + 1]);

    uint4* dst = reinterpret_cast<uint4*>(g_trans + toff + (size_t)local * 16);
    uint4 a, b;
    a.x = *(uint32_t*)&hv[0]; a.y = *(uint32_t*)&hv[1];
    a.z = *(uint32_t*)&hv[2]; a.w = *(uint32_t*)&hv[3];
    b.x = *(uint32_t*)&hv[4]; b.y = *(uint32_t*)&hv[5];
    b.z = *(uint32_t*)&hv[6]; b.w = *(uint32_t*)&hv[7];
    dst[0] = a;
    dst[1] = b;
}

// -------- main sample kernel: 4 lanes per sample --------
// lane r in group: bit0 = feature half (16B chunk), bit1 = x-corner.
// Each lane loads its 16B chunk for BOTH y-rows (coalesced 64B row segments),
// lerps in y in-lane, scales by its x-weight, shfl_xor(2) combines x-corners.
__global__ void __launch_bounds__(256) sample_k(const float* __restrict__ pts,
                                                const float* __restrict__ radius,
                                                float* __restrict__ out) {
    int t = blockIdx.x * blockDim.x + threadIdx.x;
    int g = t >> 2;               // sample id = n*12 + j  (48M threads, exact)
    int r = t & 3;
    int n = g / 12;
    int j = g - n * 12;
    int sIdx = j / 3;             // 0..3
    int ci = j - sIdx * 3;        // 0..2
    int H = 128 << sIdx;

    float xv = __ldg(pts + n * 3 + ci);
    float yv = __ldg(radius + n);

    float fx = (xv + 1.0f) * 0.5f * 63.0f;
    float fy = (yv + 1.0f) * 0.5f * (float)(H - 1);
    float x0f = floorf(fx);
    float y0f = floorf(fy);
    float wx = fx - x0f;
    float wy = fy - y0f;
    int x0 = min(max((int)x0f, 0), 63);
    int x1 = min(x0 + 1, 63);
    int y0 = min(max((int)y0f, 0), H - 1);
    int y1 = min(y0 + 1, H - 1);

    int xs = (r & 2) ? x1 : x0;
    int hsel = (r & 1) * 8;       // feature-half offset in halfs

    int toff = 393216 * ((1 << sIdx) - 1);
    const __half* tb = g_trans + toff + (size_t)(ci * H) * (WRES * 16);

    const uint4* pA = reinterpret_cast<const uint4*>(tb + (size_t)(y0 * WRES + xs) * 16 + hsel);
    const uint4* pB = reinterpret_cast<const uint4*>(tb + (size_t)(y1 * WRES + xs) * 16 + hsel);
    uint4 vA = *pA;               // row y0, this lane's 16B chunk
    uint4 vB = *pB;               // row y1

    float wxr = (r & 2) ? wx : (1.0f - wx);
    float w0 = (1.0f - wy) * wxr;
    float w1 = wy * wxr;

    const __half2* hA = reinterpret_cast<const __half2*>(&vA);
    const __half2* hB = reinterpret_cast<const __half2*>(&vB);
    float acc[8];
#pragma unroll
    for (int k = 0; k < 4; k++) {
        float2 a = __half22float2(hA[k]);
        float2 b = __half22float2(hB[k]);
        acc[2 * k]     = a.x * w0 + b.x * w1;
        acc[2 * k + 1] = a.y * w0 + b.y * w1;
    }

    // combine the two x-corners (lane bit1)
#pragma unroll
    for (int i = 0; i < 8; i++) acc[i] += __shfl_xor_sync(0xffffffffu, acc[i], 2);

    // store one 16B quarter per lane:
    // chunk index = (r&1)*2 + (r>>1); data = (r&2) ? acc[4..7] : acc[0..3]
    int chunk = ((r & 1) << 1) | (r >> 1);
    float4 st = (r & 2) ? make_float4(acc[4], acc[5], acc[6], acc[7])
                        : make_float4(acc[0], acc[1], acc[2], acc[3]);
    float4* o = reinterpret_cast<float4*>(out + (size_t)n * 192 + j * 16 + chunk * 4);
    *o = st;
}

extern "C" void kernel_launch(void* const* d_in, const int* in_sizes, int n_in,
                              void* d_out, int out_size) {
    const float* pts    = (const float*)d_in[0];
    const float* radius = (const float*)d_in[1];
    float* out = (float*)d_out;

    transpose_all<<<(368640 + 255) / 256, 256>>>((const float*)d_in[2],
                                                 (const float*)d_in[3],
                                                 (const float*)d_in[4],
                                                 (const float*)d_in[5]);

    // NSAMP*4 = 48,000,000 threads; 256/block -> 187500 blocks exactly
    sample_k<<<187500, 256>>>(pts, radius, out);
}